// round 13
// baseline (speedup 1.0000x reference)
#include <cuda_runtime.h>
#include <math.h>

#define N_TOT 4096
#define C_DIM 256
#define K_NEG 128
#define HW 1024
#define INV_T (1.0f / 0.07f)
#define Q8 256.0f                        // int8 quant scale for both q and k
#define NEG_SCALE (INV_T / (Q8 * Q8))    // logit scale for int dots
#define NEG_INF (-1e30f)
#define FIX_SCALE 4294967296.0           // 2^32
#define GRID 512

// Scratch (allocation-free rule: __device__ globals)
__device__ __align__(16) signed char g_kn8[N_TOT * C_DIM]; // k int8*256
__device__ unsigned long long g_acc;    // fixed-point loss sum
__device__ unsigned int g_sync;         // grid-barrier arrive counter
__device__ unsigned int g_done;         // completion counter (resets g_sync)

__device__ __forceinline__ signed char q8(float v) {
    int iv = __float2int_rn(v * Q8);
    iv = max(-127, min(127, iv));
    return (signed char)iv;
}

struct SmemA {                            // phase A: normalize/transpose
    float tq[C_DIM][9];
    float tk[C_DIM][9];
    float ssq[32][8], ssk[32][8], sdt[32][8];
    float sinvq[8], sinvk[8];
};
struct SmemB {                            // phase B: logits + reductions
    float slog[2][132];
    float red[2][4];
};

// ---------------------------------------------------------------------------
// ONE persistent kernel. Block b owns positions [8b, 8b+8).
// Phase A: normalize q,k over C for the tile; k int8 -> global, q int8 +
//          l_pos -> smem (consumed locally in phase B).
// Grid barrier (all k rows visible), then
// Phase B: R10 gather-dot loop (frozen winner), 2 groups x 4 iterations.
// ---------------------------------------------------------------------------
__global__ void __launch_bounds__(256, 4) patchnce_fused_kernel(
    const float* __restrict__ fq, const float* __restrict__ fk,
    const int* __restrict__ negs, float* __restrict__ out)
{
    __shared__ union { SmemA a; SmemB b; } sm;
    __shared__ uint2 sq8[8][32];          // 8 q rows, int8 (256 B each)
    __shared__ float slpos[8];            // fp32 positive logits

    const int tid = threadIdx.x;
    const int n0  = blockIdx.x * 8;       // 8 | 1024, tile never crosses batch

    // ======================= Phase A (R5-proven layout) =====================
    {
        const int tx = tid & 7;           // 0..7 : hw within tile
        const int ty = tid >> 3;          // 0..31: channel group
        if (blockIdx.x == 0 && tid == 0) g_acc = 0ull;

        const int b   = n0 / HW;
        const int hw0 = n0 % HW;
        const size_t boff = (size_t)b * C_DIM * HW + hw0 + tx;
        const float* bq = fq + boff;
        const float* bk = fk + boff;

        float aq = 0.f, ak = 0.f, ad = 0.f;
        #pragma unroll
        for (int cc = 0; cc < 8; cc++) {  // 16 loads in flight per thread
            int c = cc * 32 + ty;
            float vq = bq[(size_t)c * HW];
            float vk = bk[(size_t)c * HW];
            sm.a.tq[c][tx] = vq;
            sm.a.tk[c][tx] = vk;
            aq += vq * vq;
            ak += vk * vk;
            ad += vq * vk;
        }
        sm.a.ssq[ty][tx] = aq;
        sm.a.ssk[ty][tx] = ak;
        sm.a.sdt[ty][tx] = ad;
        __syncthreads();

        if (ty == 0) {
            float sq = 0.f, sk = 0.f, sd = 0.f;
            #pragma unroll
            for (int r = 0; r < 32; r++) {
                sq += sm.a.ssq[r][tx];
                sk += sm.a.ssk[r][tx];
                sd += sm.a.sdt[r][tx];
            }
            float iq = rsqrtf(fmaxf(sq, 1e-24f));   // 1/max(||v||,1e-12)
            float ik = rsqrtf(fmaxf(sk, 1e-24f));
            sm.a.sinvq[tx] = iq;
            sm.a.sinvk[tx] = ik;
            slpos[tx] = sd * iq * ik * INV_T;       // fp32 positive logit
        }
        __syncthreads();

        const int c = ty * 8 + tx;        // thread owns one channel == tid
        #pragma unroll
        for (int r = 0; r < 8; r++) {
            g_kn8[(size_t)(n0 + r) * C_DIM + c] =
                q8(sm.a.tk[c][r] * sm.a.sinvk[r]);
            ((signed char*)sq8[r])[c] =             // q stays in smem
                q8(sm.a.tq[c][r] * sm.a.sinvq[r]);
        }
    }

    // ========================== grid barrier ================================
    __threadfence();                      // publish this thread's k stores
    __syncthreads();
    if (tid == 0) {
        atomicAdd(&g_sync, 1u);
        while (atomicAdd(&g_sync, 0u) < GRID) __nanosleep(64);
        __threadfence();                  // acquire
    }
    __syncthreads();                      // release block into phase B

    // ======================= Phase B (frozen R10 loop) ======================
    const int g    = tid >> 7;            // group 0/1 (warps 0-3 / 4-7)
    const int t1   = tid & 127;
    const int lane = t1 & 31;
    const int warp = t1 >> 5;
    const uint2* __restrict__ kb = (const uint2*)g_kn8;

    #pragma unroll 1
    for (int it = 0; it < 4; it++) {
        const int nl = it * 2 + g;        // local position 0..7
        const int n  = n0 + nl;
        const uint2 qv = sq8[nl][lane];   // q from smem, no global read
        if (t1 == 0) sm.b.slog[g][0] = slpos[nl];

        int myidx = negs[(size_t)n * K_NEG + warp * 32 + lane];
        myidx += (myidx >= n) ? 1 : 0;    // self-exclusion shift

        uint2 kv[8];                      // 8-deep rotating prefetch
        #pragma unroll
        for (int j = 0; j < 8; j++) {
            const int ix = __shfl_sync(0xffffffffu, myidx, j);
            kv[j] = __ldg(kb + (size_t)ix * 32 + lane);
        }
        #pragma unroll
        for (int j = 0; j < 32; j++) {
            const uint2 v = kv[j & 7];
            if (j < 24) {
                const int ix = __shfl_sync(0xffffffffu, myidx, j + 8);
                kv[j & 7] = __ldg(kb + (size_t)ix * 32 + lane);
            }
            int d = __dp4a((int)v.x, (int)qv.x, 0);
            d     = __dp4a((int)v.y, (int)qv.y, d);
            d = __reduce_add_sync(0xffffffffu, d);
            if (lane == 0)
                sm.b.slog[g][1 + warp * 32 + j] = (float)d * NEG_SCALE;
        }
        asm volatile("bar.sync %0, 128;" :: "r"(g + 1) : "memory");

        // logsumexp over 129 logits (t1==0 also covers slog[128])
        const float x     = sm.b.slog[g][t1];
        const float extra = (t1 == 0) ? sm.b.slog[g][128] : NEG_INF;

        float mx = fmaxf(x, extra);
        #pragma unroll
        for (int o = 16; o > 0; o >>= 1)
            mx = fmaxf(mx, __shfl_xor_sync(0xffffffffu, mx, o));
        if (lane == 0) sm.b.red[g][warp] = mx;
        asm volatile("bar.sync %0, 128;" :: "r"(g + 1) : "memory");
        mx = fmaxf(fmaxf(sm.b.red[g][0], sm.b.red[g][1]),
                   fmaxf(sm.b.red[g][2], sm.b.red[g][3]));
        asm volatile("bar.sync %0, 128;" :: "r"(g + 1) : "memory");

        float e = expf(x - mx) + ((t1 == 0) ? expf(extra - mx) : 0.f);
        #pragma unroll
        for (int o = 16; o > 0; o >>= 1)
            e += __shfl_xor_sync(0xffffffffu, e, o);
        if (lane == 0) sm.b.red[g][warp] = e;
        asm volatile("bar.sync %0, 128;" :: "r"(g + 1) : "memory");

        if (t1 == 0) {
            float s = sm.b.red[g][0] + sm.b.red[g][1]
                    + sm.b.red[g][2] + sm.b.red[g][3];
            float rowloss = mx + logf(s) - sm.b.slog[g][0];  // >= 0 always
            atomicAdd(&g_acc,
                (unsigned long long)llrintf(rowloss * (float)FIX_SCALE));
        }
        // WAR protection before next iteration reuses slog/red
        asm volatile("bar.sync %0, 128;" :: "r"(g + 1) : "memory");
    }

    // =================== completion: mean + counter reset ===================
    __syncthreads();
    if (tid == 0) {
        __threadfence();
        unsigned int t = atomicAdd(&g_done, 1u);
        if (t == (unsigned int)(GRID - 1)) {
            unsigned long long total = atomicAdd(&g_acc, 0ull);
            out[0] = (float)((double)total * (1.0 / FIX_SCALE) * (1.0 / N_TOT));
            g_done = 0u;                  // reset for next graph replay
            g_sync = 0u;
        }
    }
}

// ---------------------------------------------------------------------------
extern "C" void kernel_launch(void* const* d_in, const int* in_sizes, int n_in,
                              void* d_out, int out_size)
{
    const float* fq   = (const float*)d_in[0];
    const float* fk   = (const float*)d_in[1];
    const int*   negs = (const int*)d_in[2];
    float*       out  = (float*)d_out;

    patchnce_fused_kernel<<<GRID, 256>>>(fq, fk, negs, out);
}

// round 14
// speedup vs baseline: 1.1810x; 1.1810x over previous
#include <cuda_runtime.h>
#include <math.h>

#define N_TOT 4096
#define C_DIM 256
#define K_NEG 128
#define HW 1024
#define INV_T (1.0f / 0.07f)
#define Q8 256.0f                        // int8 quant scale for both q and k
#define NEG_SCALE (INV_T / (Q8 * Q8))    // logit scale for int dots
#define NEG_INF (-1e30f)
#define FIX_SCALE 4294967296.0           // 2^32

// Scratch (allocation-free rule: __device__ globals)
__device__ __align__(16) signed char g_qn8[N_TOT * C_DIM]; // q int8*256
__device__ __align__(16) signed char g_kn8[N_TOT * C_DIM]; // k int8*256
__device__ float g_lpos[N_TOT];                             // l_pos logit (fp32)
__device__ unsigned long long g_acc;                        // fixed-point loss sum
__device__ unsigned int       g_done;                       // block completion ctr

__device__ __forceinline__ signed char q8(float v) {
    int iv = __float2int_rn(v * Q8);
    iv = max(-127, min(127, iv));
    return (signed char)iv;
}

// ---------------------------------------------------------------------------
// K1: normalize q,k over C, transpose [B,C,HW] -> [N,C] int8, fp32 l_pos.
// float4 loads along contiguous hw. Block (2,128), 8-position tiles, grid 512.
// (frozen R12 version)
// ---------------------------------------------------------------------------
__global__ void __launch_bounds__(256) norm_transpose_kernel(
    const float* __restrict__ fq, const float* __restrict__ fk)
{
    const int tx  = threadIdx.x;          // 0..1  : float4 group within 8 hw
    const int ty  = threadIdx.y;          // 0..127: channel (and +128)
    const int tid = ty * 2 + tx;          // 0..255

    if (blockIdx.x == 0 && tid == 0) g_acc = 0ull;

    const int n0  = blockIdx.x * 8;       // 8 | 1024, tile never crosses batch
    const int b   = n0 / HW;
    const int hw0 = n0 % HW;

    __shared__ float tq[C_DIM][9];        // [c][pos], odd stride
    __shared__ float tk[C_DIM][9];
    __shared__ float psq[128][9], psk[128][9], psd[128][9]; // [ty][pos]
    __shared__ float sinvq[8], sinvk[8];

    const size_t base = (size_t)b * C_DIM * HW + hw0 + tx * 4;

    float aq[4] = {0,0,0,0}, ak[4] = {0,0,0,0}, ad[4] = {0,0,0,0};
    #pragma unroll
    for (int c2 = 0; c2 < 2; c2++) {
        const int c = c2 * 128 + ty;
        const float4 vq = *(const float4*)(fq + base + (size_t)c * HW);
        const float4 vk = *(const float4*)(fk + base + (size_t)c * HW);
        tq[c][tx*4+0] = vq.x; tq[c][tx*4+1] = vq.y;
        tq[c][tx*4+2] = vq.z; tq[c][tx*4+3] = vq.w;
        tk[c][tx*4+0] = vk.x; tk[c][tx*4+1] = vk.y;
        tk[c][tx*4+2] = vk.z; tk[c][tx*4+3] = vk.w;
        const float q4[4] = {vq.x, vq.y, vq.z, vq.w};
        const float k4[4] = {vk.x, vk.y, vk.z, vk.w};
        #pragma unroll
        for (int i = 0; i < 4; i++) {
            aq[i] += q4[i] * q4[i];
            ak[i] += k4[i] * k4[i];
            ad[i] += q4[i] * k4[i];
        }
    }
    #pragma unroll
    for (int i = 0; i < 4; i++) {
        psq[ty][tx*4+i] = aq[i];
        psk[ty][tx*4+i] = ak[i];
        psd[ty][tx*4+i] = ad[i];
    }
    __syncthreads();

    {
        const int warp = tid >> 5;        // 0..7 == position
        const int lane = tid & 31;
        float sq = psq[lane][warp] + psq[lane + 32][warp]
                 + psq[lane + 64][warp] + psq[lane + 96][warp];
        float sk = psk[lane][warp] + psk[lane + 32][warp]
                 + psk[lane + 64][warp] + psk[lane + 96][warp];
        float sd = psd[lane][warp] + psd[lane + 32][warp]
                 + psd[lane + 64][warp] + psd[lane + 96][warp];
        #pragma unroll
        for (int o = 16; o > 0; o >>= 1) {
            sq += __shfl_xor_sync(0xffffffffu, sq, o);
            sk += __shfl_xor_sync(0xffffffffu, sk, o);
            sd += __shfl_xor_sync(0xffffffffu, sd, o);
        }
        if (lane == 0) {
            float iq = rsqrtf(fmaxf(sq, 1e-24f));  // 1/max(||v||,1e-12)
            float ik = rsqrtf(fmaxf(sk, 1e-24f));
            sinvq[warp] = iq;
            sinvk[warp] = ik;
            g_lpos[n0 + warp] = sd * iq * ik * INV_T;
        }
    }
    __syncthreads();

    #pragma unroll
    for (int r = 0; r < 8; r++) {
        const size_t o = (size_t)(n0 + r) * C_DIM + tid;
        g_qn8[o] = q8(tq[tid][r] * sinvq[r]);
        g_kn8[o] = q8(tk[tid][r] * sinvk[r]);
    }
}

// ---------------------------------------------------------------------------
// K2: per-row gather-dot — R10 gather core (8-deep rotating prefetch,
// uint2/lane, full-warp REDUX) with REGISTER-RESIDENT logits:
// lane j of each warp keeps logit j (REDUX broadcasts the sum to all lanes),
// eliminating the per-negative STS and the smem logit array entirely.
// Epilogue: warp-local shuffle max/expsum over lval, cross-warp via 4-float
// smem. One block (128 thr) per position n; fused deterministic mean.
// ---------------------------------------------------------------------------
__global__ void __launch_bounds__(128) patchnce_main_kernel(
    const int* __restrict__ negs, float* __restrict__ out)
{
    const int n    = blockIdx.x;
    const int tid  = threadIdx.x;
    const int lane = tid & 31;
    const int warp = tid >> 5;

    __shared__ float redmx[4];
    __shared__ float rede[4];

    const uint2* __restrict__ kb = (const uint2*)g_kn8;

    // this lane's 8 q channels, int8
    const uint2 qv = __ldg((const uint2*)(g_qn8 + n * (C_DIM / 8)) + lane);

    // l_pos: broadcast to all lanes of warp 0 (participates in max there)
    const float lp = (warp == 0) ? g_lpos[n] : NEG_INF;

    // per-lane negative index (lane l of warp w owns broadcast slot l)
    int myidx = negs[n * K_NEG + warp * 32 + lane];
    myidx += (myidx >= n) ? 1 : 0;        // self-exclusion shift

    // prologue: fill the 8-deep pipeline
    uint2 kv[8];
    #pragma unroll
    for (int j = 0; j < 8; j++) {
        const int ix = __shfl_sync(0xffffffffu, myidx, j);
        kv[j] = __ldg(kb + ix * 32 + lane);
    }

    float lval = NEG_INF;                 // this lane's logit (set once, j==lane)
    #pragma unroll
    for (int j = 0; j < 32; j++) {
        const uint2 v = kv[j & 7];        // consume (copy before refill)
        if (j < 24) {                     // refill slot before the reduction
            const int ix = __shfl_sync(0xffffffffu, myidx, j + 8);
            kv[j & 7] = __ldg(kb + ix * 32 + lane);
        }
        int d = __dp4a((int)v.x, (int)qv.x, 0);
        d     = __dp4a((int)v.y, (int)qv.y, d);
        d = __reduce_add_sync(0xffffffffu, d);    // sum broadcast to ALL lanes
        if (lane == j) lval = (float)d * NEG_SCALE;  // predicated reg write
    }

    // ---- logsumexp: warp-local on registers, cross-warp via 4 floats ----
    float mx = fmaxf(lval, lp);           // warp0 lanes fold in l_pos
    #pragma unroll
    for (int o = 16; o > 0; o >>= 1)
        mx = fmaxf(mx, __shfl_xor_sync(0xffffffffu, mx, o));
    if (lane == 0) redmx[warp] = mx;
    __syncthreads();
    const float MX = fmaxf(fmaxf(redmx[0], redmx[1]),
                           fmaxf(redmx[2], redmx[3]));

    float e = expf(lval - MX);
    if (tid == 0) e += expf(lp - MX);     // l_pos term, once
    #pragma unroll
    for (int o = 16; o > 0; o >>= 1)
        e += __shfl_xor_sync(0xffffffffu, e, o);
    if (lane == 0) rede[warp] = e;
    __syncthreads();

    if (tid == 0) {
        float s = rede[0] + rede[1] + rede[2] + rede[3];
        float rowloss = MX + logf(s) - lp;        // >= 0 always
        unsigned long long fx =
            (unsigned long long)llrintf(rowloss * (float)FIX_SCALE);
        atomicAdd(&g_acc, fx);            // integer atomics commute: deterministic
        __threadfence();
        unsigned int t = atomicAdd(&g_done, 1u);
        if (t == (unsigned int)(gridDim.x - 1)) {
            unsigned long long total = atomicAdd(&g_acc, 0ull);
            out[0] = (float)((double)total * (1.0 / FIX_SCALE) * (1.0 / N_TOT));
            g_done = 0u;                  // reset for next graph replay
        }
    }
}

// ---------------------------------------------------------------------------
extern "C" void kernel_launch(void* const* d_in, const int* in_sizes, int n_in,
                              void* d_out, int out_size)
{
    const float* fq   = (const float*)d_in[0];
    const float* fk   = (const float*)d_in[1];
    const int*   negs = (const int*)d_in[2];
    float*       out  = (float*)d_out;

    norm_transpose_kernel<<<512, dim3(2, 128)>>>(fq, fk);
    patchnce_main_kernel<<<N_TOT, 128>>>(negs, out);
}